// round 1
// baseline (speedup 1.0000x reference)
#include <cuda_runtime.h>
#include <math.h>
#include <stdint.h>

#define DIM    3072
#define NHEADS 24
#define HDIM   128
#define SEQ    2304

// ---------------------------------------------------------------------------
// Scratch (allocation-free: __device__ globals)
// ---------------------------------------------------------------------------
__device__ float g_q[SEQ * DIM];
__device__ float g_k[SEQ * DIM];
__device__ float g_v[SEQ * DIM];
__device__ float g_attn[SEQ * DIM];

// ---------------------------------------------------------------------------
// GEMM (NT): C[m][n] = sum_k A[m][k] * B[n][k] + bias[n]
// BM=BN=128, BK=16, 256 threads, 8x8 microtile per thread.
// ---------------------------------------------------------------------------
__global__ __launch_bounds__(256, 2)
void gemm_nt_bias(const float* __restrict__ A, const float* __restrict__ B,
                  const float* __restrict__ bias, float* __restrict__ C,
                  int M, int N, int K) {
    __shared__ float As[16][128];
    __shared__ float Bs[16][128];

    const int bm = blockIdx.y * 128;
    const int bn = blockIdx.x * 128;
    const int tid = threadIdx.x;
    const int ty = tid >> 4;          // 0..15
    const int tx = tid & 15;          // 0..15
    const int m0 = ty * 8;
    const int n0 = tx * 8;
    const int lr = tid >> 2;          // 0..63  (loader row)
    const int lc = (tid & 3) << 2;    // 0,4,8,12 (loader k-col, float4)

    float acc[8][8];
#pragma unroll
    for (int i = 0; i < 8; i++)
#pragma unroll
        for (int j = 0; j < 8; j++) acc[i][j] = 0.f;

    const float* Aptr = A + (size_t)(bm + lr) * K + lc;
    const float* Bptr = B + (size_t)(bn + lr) * K + lc;
    const size_t a64 = (size_t)64 * K;

    for (int kt = 0; kt < K; kt += 16) {
        float4 a0 = *(const float4*)(Aptr + kt);
        float4 a1 = *(const float4*)(Aptr + a64 + kt);
        float4 b0 = *(const float4*)(Bptr + kt);
        float4 b1 = *(const float4*)(Bptr + a64 + kt);
        __syncthreads();   // previous iteration's smem reads complete
        As[lc + 0][lr] = a0.x; As[lc + 1][lr] = a0.y;
        As[lc + 2][lr] = a0.z; As[lc + 3][lr] = a0.w;
        As[lc + 0][lr + 64] = a1.x; As[lc + 1][lr + 64] = a1.y;
        As[lc + 2][lr + 64] = a1.z; As[lc + 3][lr + 64] = a1.w;
        Bs[lc + 0][lr] = b0.x; Bs[lc + 1][lr] = b0.y;
        Bs[lc + 2][lr] = b0.z; Bs[lc + 3][lr] = b0.w;
        Bs[lc + 0][lr + 64] = b1.x; Bs[lc + 1][lr + 64] = b1.y;
        Bs[lc + 2][lr + 64] = b1.z; Bs[lc + 3][lr + 64] = b1.w;
        __syncthreads();
#pragma unroll
        for (int kk = 0; kk < 16; kk++) {
            float4 av0 = *(const float4*)&As[kk][m0];
            float4 av1 = *(const float4*)&As[kk][m0 + 4];
            float4 bv0 = *(const float4*)&Bs[kk][n0];
            float4 bv1 = *(const float4*)&Bs[kk][n0 + 4];
            float a[8] = {av0.x, av0.y, av0.z, av0.w, av1.x, av1.y, av1.z, av1.w};
            float b[8] = {bv0.x, bv0.y, bv0.z, bv0.w, bv1.x, bv1.y, bv1.z, bv1.w};
#pragma unroll
            for (int i = 0; i < 8; i++)
#pragma unroll
                for (int j = 0; j < 8; j++) acc[i][j] += a[i] * b[j];
        }
    }

    float bv[8];
#pragma unroll
    for (int j = 0; j < 8; j++) bv[j] = bias[bn + n0 + j];
#pragma unroll
    for (int i = 0; i < 8; i++) {
        float* Crow = C + (size_t)(bm + m0 + i) * N + bn + n0;
        float4 o0 = make_float4(acc[i][0] + bv[0], acc[i][1] + bv[1],
                                acc[i][2] + bv[2], acc[i][3] + bv[3]);
        float4 o1 = make_float4(acc[i][4] + bv[4], acc[i][5] + bv[5],
                                acc[i][6] + bv[6], acc[i][7] + bv[7]);
        *(float4*)(Crow)     = o0;
        *(float4*)(Crow + 4) = o1;
    }
}

// ---------------------------------------------------------------------------
// Fused fp32 RMSNorm (over full DIM) + 3-axis RoPE, in place. 1 block per row.
// ---------------------------------------------------------------------------
__global__ __launch_bounds__(256)
void norm_rope(float* __restrict__ buf, const float* __restrict__ g,
               const float* __restrict__ freqs, const int* __restrict__ grid_sizes) {
    __shared__ float red[256];
    __shared__ float s_rn;
    const int row = blockIdx.x;
    const int tid = threadIdx.x;
    float* rp = buf + (size_t)row * DIM;

    float ss = 0.f;
    for (int i = tid; i < DIM; i += 256) { float v = rp[i]; ss += v * v; }
    red[tid] = ss;
    __syncthreads();
#pragma unroll
    for (int st = 128; st > 0; st >>= 1) {
        if (tid < st) red[tid] += red[tid + st];
        __syncthreads();
    }
    if (tid == 0) s_rn = rsqrtf(red[0] / (float)DIM + 1e-6f);
    __syncthreads();
    const float rn = s_rn;

    const int gh = grid_sizes[1];
    const int gw = grid_sizes[2];
    const int fi = row / (gh * gw);
    const int hi = (row % (gh * gw)) / gw;
    const int wi = row % gw;

    for (int p = tid; p < DIM / 2; p += 256) {
        const int c = p & 63;                         // rotary pair index in head
        const int pos = (c < 22) ? fi : ((c < 43) ? hi : wi);
        const float theta = freqs[pos * 64 + c];
        float sn, cs;
        sincosf(theta, &sn, &cs);
        const int idx = (p >> 6) * HDIM + 2 * c;      // head*128 + 2c
        const float xr = rp[idx]     * rn * g[idx];
        const float xi = rp[idx + 1] * rn * g[idx + 1];
        rp[idx]     = xr * cs - xi * sn;
        rp[idx + 1] = xr * sn + xi * cs;
    }
}

// ---------------------------------------------------------------------------
// Flash attention (fp32, online softmax). BQ=BK=64, D=128, 256 threads.
// Grid: (SEQ/64, NHEADS). smem ~117 KB (dynamic).
// ---------------------------------------------------------------------------
#define QKV_STRIDE 132   // 128 + 4 pad (keeps float4 alignment, breaks bank cycle)
#define PS_STRIDE  68

__global__ __launch_bounds__(256, 1)
void flash_kernel(const float* __restrict__ Q, const float* __restrict__ K,
                  const float* __restrict__ V, const int* __restrict__ seq_lens,
                  float* __restrict__ O) {
    extern __shared__ float sm[];
    float* Qs   = sm;                       // [64][132]
    float* Ks   = Qs + 64 * QKV_STRIDE;     // [64][132]
    float* Vs   = Ks + 64 * QKV_STRIDE;     // [64][132]
    float* Ps   = Vs + 64 * QKV_STRIDE;     // [64][68]
    float* rowm = Ps + 64 * PS_STRIDE;      // [64]
    float* rowl = rowm + 64;                // [64]
    float* rowa = rowl + 64;                // [64]

    const int head = blockIdx.y;
    const int q0 = blockIdx.x * 64;
    const int tid = threadIdx.x;
    const int ty = tid >> 4;   // 0..15 -> rows ty*4..ty*4+3
    const int tx = tid & 15;   // 0..15
    const int seqlen = seq_lens[0];
    const float scale = 0.08838834764831845f;  // 1/sqrt(128)

    // Load Q tile (pre-scaled)
    for (int i = tid; i < 64 * 128; i += 256) {
        const int r = i >> 7, d = i & 127;
        Qs[r * QKV_STRIDE + d] = Q[(size_t)(q0 + r) * DIM + head * HDIM + d] * scale;
    }
    if (tid < 64) { rowm[tid] = -1e30f; rowl[tid] = 0.f; }

    float o[4][8];
#pragma unroll
    for (int i = 0; i < 4; i++)
#pragma unroll
        for (int j = 0; j < 8; j++) o[i][j] = 0.f;

    for (int k0 = 0; k0 < SEQ; k0 += 64) {
        __syncthreads();   // prev PV reads of Vs/Ps done; Qs/rowm init visible
        for (int i = tid; i < 64 * 128; i += 256) {
            const int r = i >> 7, d = i & 127;
            const size_t src = (size_t)(k0 + r) * DIM + head * HDIM + d;
            Ks[r * QKV_STRIDE + d] = K[src];
            Vs[r * QKV_STRIDE + d] = V[src];
        }
        __syncthreads();

        // --- scores: s[i][j] = q_row(ty*4+i) . k_col(tx+16j) ---
        float s[4][4];
#pragma unroll
        for (int i = 0; i < 4; i++)
#pragma unroll
            for (int j = 0; j < 4; j++) s[i][j] = 0.f;

        for (int d = 0; d < 128; d += 4) {
            float4 qv[4], kv[4];
#pragma unroll
            for (int i = 0; i < 4; i++)
                qv[i] = *(const float4*)&Qs[(ty * 4 + i) * QKV_STRIDE + d];
#pragma unroll
            for (int j = 0; j < 4; j++)
                kv[j] = *(const float4*)&Ks[(tx + 16 * j) * QKV_STRIDE + d];
#pragma unroll
            for (int i = 0; i < 4; i++)
#pragma unroll
                for (int j = 0; j < 4; j++)
                    s[i][j] += qv[i].x * kv[j].x + qv[i].y * kv[j].y +
                               qv[i].z * kv[j].z + qv[i].w * kv[j].w;
        }
#pragma unroll
        for (int i = 0; i < 4; i++)
#pragma unroll
            for (int j = 0; j < 4; j++)
                Ps[(ty * 4 + i) * PS_STRIDE + tx + 16 * j] = s[i][j];
        __syncthreads();

        // --- online softmax row pass (threads 0..63) ---
        if (tid < 64) {
            const int r = tid;
            int kvalid = seqlen - k0;
            kvalid = kvalid > 64 ? 64 : (kvalid < 0 ? 0 : kvalid);
            float mo = rowm[r], mn = mo;
            for (int j = 0; j < kvalid; j++) mn = fmaxf(mn, Ps[r * PS_STRIDE + j]);
            const float a = __expf(mo - mn);
            float l = rowl[r] * a;
            for (int j = 0; j < 64; j++) {
                const float p = (j < kvalid) ? __expf(Ps[r * PS_STRIDE + j] - mn) : 0.f;
                Ps[r * PS_STRIDE + j] = p;
                l += p;
            }
            rowm[r] = mn; rowl[r] = l; rowa[r] = a;
        }
        __syncthreads();

        // --- PV: o[rows ty*4+i][cols tx*8..tx*8+7] ---
#pragma unroll
        for (int i = 0; i < 4; i++) {
            const float ai = rowa[ty * 4 + i];
#pragma unroll
            for (int j = 0; j < 8; j++) o[i][j] *= ai;
        }
        for (int j = 0; j < 64; j++) {
            const float4 v0 = *(const float4*)&Vs[j * QKV_STRIDE + tx * 8];
            const float4 v1 = *(const float4*)&Vs[j * QKV_STRIDE + tx * 8 + 4];
#pragma unroll
            for (int i = 0; i < 4; i++) {
                const float p = Ps[(ty * 4 + i) * PS_STRIDE + j];
                o[i][0] += p * v0.x; o[i][1] += p * v0.y;
                o[i][2] += p * v0.z; o[i][3] += p * v0.w;
                o[i][4] += p * v1.x; o[i][5] += p * v1.y;
                o[i][6] += p * v1.z; o[i][7] += p * v1.w;
            }
        }
    }

#pragma unroll
    for (int i = 0; i < 4; i++) {
        const int r = ty * 4 + i;
        const float linv = 1.f / rowl[r];
        float* dst = O + (size_t)(q0 + r) * DIM + head * HDIM + tx * 8;
        float4 o0 = make_float4(o[i][0] * linv, o[i][1] * linv,
                                o[i][2] * linv, o[i][3] * linv);
        float4 o1 = make_float4(o[i][4] * linv, o[i][5] * linv,
                                o[i][6] * linv, o[i][7] * linv);
        *(float4*)(dst)     = o0;
        *(float4*)(dst + 4) = o1;
    }
}

// ---------------------------------------------------------------------------
// Launch
// ---------------------------------------------------------------------------
extern "C" void kernel_launch(void* const* d_in, const int* in_sizes, int n_in,
                              void* d_out, int out_size) {
    const float* x         = (const float*)d_in[0];
    const int*   seq_lens  = (const int*)  d_in[1];
    const int*   grid_sz   = (const int*)  d_in[2];
    const float* freqs     = (const float*)d_in[3];
    const float* wq        = (const float*)d_in[4];
    const float* bq        = (const float*)d_in[5];
    const float* wk        = (const float*)d_in[6];
    const float* bk        = (const float*)d_in[7];
    const float* wv        = (const float*)d_in[8];
    const float* bv        = (const float*)d_in[9];
    const float* wo        = (const float*)d_in[10];
    const float* bo        = (const float*)d_in[11];
    const float* gq        = (const float*)d_in[12];
    const float* gk        = (const float*)d_in[13];
    float* out = (float*)d_out;

    float *q, *k, *v, *attn;
    cudaGetSymbolAddress((void**)&q,    g_q);
    cudaGetSymbolAddress((void**)&k,    g_k);
    cudaGetSymbolAddress((void**)&v,    g_v);
    cudaGetSymbolAddress((void**)&attn, g_attn);

    const dim3 gemm_grid(DIM / 128, SEQ / 128);   // (24, 18)
    gemm_nt_bias<<<gemm_grid, 256>>>(x, wq, bq, q, SEQ, DIM, DIM);
    gemm_nt_bias<<<gemm_grid, 256>>>(x, wk, bk, k, SEQ, DIM, DIM);
    gemm_nt_bias<<<gemm_grid, 256>>>(x, wv, bv, v, SEQ, DIM, DIM);

    norm_rope<<<SEQ, 256>>>(q, gq, freqs, grid_sz);
    norm_rope<<<SEQ, 256>>>(k, gk, freqs, grid_sz);

    const size_t smem = (size_t)(3 * 64 * QKV_STRIDE + 64 * PS_STRIDE + 3 * 64) * sizeof(float);
    cudaFuncSetAttribute(flash_kernel, cudaFuncAttributeMaxDynamicSharedMemorySize, (int)smem);
    flash_kernel<<<dim3(SEQ / 64, NHEADS), 256, smem>>>(q, k, v, seq_lens, attn);

    gemm_nt_bias<<<gemm_grid, 256>>>(attn, wo, bo, out, SEQ, DIM, DIM);
}

// round 2
// speedup vs baseline: 1.2990x; 1.2990x over previous
#include <cuda_runtime.h>
#include <cuda_bf16.h>
#include <math.h>
#include <stdint.h>

#define DIM    3072
#define NHEADS 24
#define HDIM   128
#define SEQ    2304

// ---------------------------------------------------------------------------
// Scratch (allocation-free: __device__ globals)
// ---------------------------------------------------------------------------
__device__ float g_q[SEQ * DIM];
__device__ float g_k[SEQ * DIM];
__device__ float g_v[SEQ * DIM];
__device__ float g_attn[SEQ * DIM];

__device__ __nv_bfloat16 g_xh[SEQ * DIM],  g_xl[SEQ * DIM];
__device__ __nv_bfloat16 g_ah[SEQ * DIM],  g_al[SEQ * DIM];
__device__ __nv_bfloat16 g_wqh[DIM * DIM], g_wql[DIM * DIM];
__device__ __nv_bfloat16 g_wkh[DIM * DIM], g_wkl[DIM * DIM];
__device__ __nv_bfloat16 g_wvh[DIM * DIM], g_wvl[DIM * DIM];
__device__ __nv_bfloat16 g_woh[DIM * DIM], g_wol[DIM * DIM];

// ---------------------------------------------------------------------------
// fp32 -> (bf16 hi, bf16 lo) split.  x ~= hi + lo, residual ~ eps_bf16^2.
// ---------------------------------------------------------------------------
__global__ __launch_bounds__(256)
void split_f32(const float* __restrict__ in, __nv_bfloat16* __restrict__ hi,
               __nv_bfloat16* __restrict__ lo, int n) {
    int i = (blockIdx.x * 256 + threadIdx.x) * 4;
    if (i + 3 >= n) return;
    float4 v = *(const float4*)(in + i);
    __nv_bfloat16 h0 = __float2bfloat16(v.x);
    __nv_bfloat16 h1 = __float2bfloat16(v.y);
    __nv_bfloat16 h2 = __float2bfloat16(v.z);
    __nv_bfloat16 h3 = __float2bfloat16(v.w);
    __nv_bfloat162 hA, hB, lA, lB;
    hA.x = h0; hA.y = h1; hB.x = h2; hB.y = h3;
    lA.x = __float2bfloat16(v.x - __bfloat162float(h0));
    lA.y = __float2bfloat16(v.y - __bfloat162float(h1));
    lB.x = __float2bfloat16(v.z - __bfloat162float(h2));
    lB.y = __float2bfloat16(v.w - __bfloat162float(h3));
    *(__nv_bfloat162*)(hi + i)     = hA;
    *(__nv_bfloat162*)(hi + i + 2) = hB;
    *(__nv_bfloat162*)(lo + i)     = lA;
    *(__nv_bfloat162*)(lo + i + 2) = lB;
}

// ---------------------------------------------------------------------------
// bf16x3 tensor-core GEMM (NT): C[m][n] = sum_k A[m][k]*B[n][k] + bias[n]
// BM=BN=128, BK=32. 256 threads = 8 warps (2M x 4N), warp tile 64x32,
// mma.sync.m16n8k16 bf16, fp32 accum. 3 passes: AhBh + AhBl + AlBh.
// ---------------------------------------------------------------------------
#define SSTR 20   // u32 stride per smem row (16 data u32 = 32 bf16, +4 pad)

#define MMA_BF16(d, a, b)                                                     \
    asm volatile("mma.sync.aligned.m16n8k16.row.col.f32.bf16.bf16.f32 "       \
                 "{%0,%1,%2,%3}, {%4,%5,%6,%7}, {%8,%9}, {%0,%1,%2,%3};"      \
                 : "+f"(d[0]), "+f"(d[1]), "+f"(d[2]), "+f"(d[3])             \
                 : "r"(a[0]), "r"(a[1]), "r"(a[2]), "r"(a[3]),                \
                   "r"(b[0]), "r"(b[1]))

__global__ __launch_bounds__(256)
void gemm_bf16x3(const __nv_bfloat16* __restrict__ Ah,
                 const __nv_bfloat16* __restrict__ Al,
                 const __nv_bfloat16* __restrict__ Bh,
                 const __nv_bfloat16* __restrict__ Bl,
                 const float* __restrict__ bias, float* __restrict__ C,
                 int M, int N, int K) {
    __shared__ uint32_t sAh[128 * SSTR], sAl[128 * SSTR];
    __shared__ uint32_t sBh[128 * SSTR], sBl[128 * SSTR];

    const int bm = blockIdx.y * 128, bn = blockIdx.x * 128;
    const int tid = threadIdx.x;
    const int w = tid >> 5, lane = tid & 31;
    const int wm = w & 1, wn = w >> 1;          // 2 x 4 warp grid
    const int g = lane >> 2, tg = lane & 3;     // group / thread-in-group

    float acc[4][4][4];
#pragma unroll
    for (int mi = 0; mi < 4; mi++)
#pragma unroll
        for (int ni = 0; ni < 4; ni++)
#pragma unroll
            for (int r = 0; r < 4; r++) acc[mi][ni][r] = 0.f;

    for (int kt = 0; kt < K; kt += 32) {
        __syncthreads();
        // cooperative tile load: 512 uint4 per matrix, 2 per thread
        int idx = tid;
#pragma unroll
        for (int it = 0; it < 2; it++, idx += 256) {
            const int row = idx >> 2, q = idx & 3;
            const size_t ga = (size_t)(bm + row) * K + kt + q * 8;
            const size_t gb = (size_t)(bn + row) * K + kt + q * 8;
            uint4 vah = *(const uint4*)(Ah + ga);
            uint4 val = *(const uint4*)(Al + ga);
            uint4 vbh = *(const uint4*)(Bh + gb);
            uint4 vbl = *(const uint4*)(Bl + gb);
            *(uint4*)&sAh[row * SSTR + q * 4] = vah;
            *(uint4*)&sAl[row * SSTR + q * 4] = val;
            *(uint4*)&sBh[row * SSTR + q * 4] = vbh;
            *(uint4*)&sBl[row * SSTR + q * 4] = vbl;
        }
        __syncthreads();

#pragma unroll
        for (int ks = 0; ks < 2; ks++) {
            const int kb = ks * 8;
            uint32_t ah[4][4], al[4][4], bh[4][2], bl[4][2];
#pragma unroll
            for (int mi = 0; mi < 4; mi++) {
                const int r = wm * 64 + mi * 16 + g;
                ah[mi][0] = sAh[r * SSTR + kb + tg];
                ah[mi][1] = sAh[(r + 8) * SSTR + kb + tg];
                ah[mi][2] = sAh[r * SSTR + kb + tg + 4];
                ah[mi][3] = sAh[(r + 8) * SSTR + kb + tg + 4];
                al[mi][0] = sAl[r * SSTR + kb + tg];
                al[mi][1] = sAl[(r + 8) * SSTR + kb + tg];
                al[mi][2] = sAl[r * SSTR + kb + tg + 4];
                al[mi][3] = sAl[(r + 8) * SSTR + kb + tg + 4];
            }
#pragma unroll
            for (int ni = 0; ni < 4; ni++) {
                const int c = wn * 32 + ni * 8 + g;
                bh[ni][0] = sBh[c * SSTR + kb + tg];
                bh[ni][1] = sBh[c * SSTR + kb + tg + 4];
                bl[ni][0] = sBl[c * SSTR + kb + tg];
                bl[ni][1] = sBl[c * SSTR + kb + tg + 4];
            }
#pragma unroll
            for (int mi = 0; mi < 4; mi++)
#pragma unroll
                for (int ni = 0; ni < 4; ni++) {
                    MMA_BF16(acc[mi][ni], ah[mi], bh[ni]);
                    MMA_BF16(acc[mi][ni], ah[mi], bl[ni]);
                    MMA_BF16(acc[mi][ni], al[mi], bh[ni]);
                }
        }
    }

#pragma unroll
    for (int mi = 0; mi < 4; mi++)
#pragma unroll
        for (int ni = 0; ni < 4; ni++) {
            const int r = bm + wm * 64 + mi * 16 + g;
            const int c = bn + wn * 32 + ni * 8 + tg * 2;
            const float b0 = bias[c], b1 = bias[c + 1];
            C[(size_t)r * N + c]           = acc[mi][ni][0] + b0;
            C[(size_t)r * N + c + 1]       = acc[mi][ni][1] + b1;
            C[(size_t)(r + 8) * N + c]     = acc[mi][ni][2] + b0;
            C[(size_t)(r + 8) * N + c + 1] = acc[mi][ni][3] + b1;
        }
}

// ---------------------------------------------------------------------------
// Fused fp32 RMSNorm (over full DIM) + 3-axis RoPE, in place. 1 block per row.
// ---------------------------------------------------------------------------
__global__ __launch_bounds__(256)
void norm_rope(float* __restrict__ buf, const float* __restrict__ g,
               const float* __restrict__ freqs, const int* __restrict__ grid_sizes) {
    __shared__ float red[256];
    __shared__ float s_rn;
    const int row = blockIdx.x;
    const int tid = threadIdx.x;
    float* rp = buf + (size_t)row * DIM;

    float ss = 0.f;
    for (int i = tid; i < DIM; i += 256) { float v = rp[i]; ss += v * v; }
    red[tid] = ss;
    __syncthreads();
#pragma unroll
    for (int st = 128; st > 0; st >>= 1) {
        if (tid < st) red[tid] += red[tid + st];
        __syncthreads();
    }
    if (tid == 0) s_rn = rsqrtf(red[0] / (float)DIM + 1e-6f);
    __syncthreads();
    const float rn = s_rn;

    const int gh = grid_sizes[1];
    const int gw = grid_sizes[2];
    const int fi = row / (gh * gw);
    const int hi = (row % (gh * gw)) / gw;
    const int wi = row % gw;

    for (int p = tid; p < DIM / 2; p += 256) {
        const int c = p & 63;
        const int pos = (c < 22) ? fi : ((c < 43) ? hi : wi);
        const float theta = freqs[pos * 64 + c];
        float sn, cs;
        sincosf(theta, &sn, &cs);
        const int idx = (p >> 6) * HDIM + 2 * c;
        const float xr = rp[idx]     * rn * g[idx];
        const float xi = rp[idx + 1] * rn * g[idx + 1];
        rp[idx]     = xr * cs - xi * sn;
        rp[idx + 1] = xr * sn + xi * cs;
    }
}

// ---------------------------------------------------------------------------
// Flash attention (fp32, online softmax). BQ=BK=64, D=128, 256 threads.
// ---------------------------------------------------------------------------
#define QKV_STRIDE 132
#define PS_STRIDE  68

__global__ __launch_bounds__(256, 1)
void flash_kernel(const float* __restrict__ Q, const float* __restrict__ K,
                  const float* __restrict__ V, const int* __restrict__ seq_lens,
                  float* __restrict__ O) {
    extern __shared__ float sm[];
    float* Qs   = sm;
    float* Ks   = Qs + 64 * QKV_STRIDE;
    float* Vs   = Ks + 64 * QKV_STRIDE;
    float* Ps   = Vs + 64 * QKV_STRIDE;
    float* rowm = Ps + 64 * PS_STRIDE;
    float* rowl = rowm + 64;
    float* rowa = rowl + 64;

    const int head = blockIdx.y;
    const int q0 = blockIdx.x * 64;
    const int tid = threadIdx.x;
    const int ty = tid >> 4;
    const int tx = tid & 15;
    const int seqlen = seq_lens[0];
    const float scale = 0.08838834764831845f;

    for (int i = tid; i < 64 * 128; i += 256) {
        const int r = i >> 7, d = i & 127;
        Qs[r * QKV_STRIDE + d] = Q[(size_t)(q0 + r) * DIM + head * HDIM + d] * scale;
    }
    if (tid < 64) { rowm[tid] = -1e30f; rowl[tid] = 0.f; }

    float o[4][8];
#pragma unroll
    for (int i = 0; i < 4; i++)
#pragma unroll
        for (int j = 0; j < 8; j++) o[i][j] = 0.f;

    for (int k0 = 0; k0 < SEQ; k0 += 64) {
        __syncthreads();
        for (int i = tid; i < 64 * 128; i += 256) {
            const int r = i >> 7, d = i & 127;
            const size_t src = (size_t)(k0 + r) * DIM + head * HDIM + d;
            Ks[r * QKV_STRIDE + d] = K[src];
            Vs[r * QKV_STRIDE + d] = V[src];
        }
        __syncthreads();

        float s[4][4];
#pragma unroll
        for (int i = 0; i < 4; i++)
#pragma unroll
            for (int j = 0; j < 4; j++) s[i][j] = 0.f;

        for (int d = 0; d < 128; d += 4) {
            float4 qv[4], kv[4];
#pragma unroll
            for (int i = 0; i < 4; i++)
                qv[i] = *(const float4*)&Qs[(ty * 4 + i) * QKV_STRIDE + d];
#pragma unroll
            for (int j = 0; j < 4; j++)
                kv[j] = *(const float4*)&Ks[(tx + 16 * j) * QKV_STRIDE + d];
#pragma unroll
            for (int i = 0; i < 4; i++)
#pragma unroll
                for (int j = 0; j < 4; j++)
                    s[i][j] += qv[i].x * kv[j].x + qv[i].y * kv[j].y +
                               qv[i].z * kv[j].z + qv[i].w * kv[j].w;
        }
#pragma unroll
        for (int i = 0; i < 4; i++)
#pragma unroll
            for (int j = 0; j < 4; j++)
                Ps[(ty * 4 + i) * PS_STRIDE + tx + 16 * j] = s[i][j];
        __syncthreads();

        if (tid < 64) {
            const int r = tid;
            int kvalid = seqlen - k0;
            kvalid = kvalid > 64 ? 64 : (kvalid < 0 ? 0 : kvalid);
            float mo = rowm[r], mn = mo;
            for (int j = 0; j < kvalid; j++) mn = fmaxf(mn, Ps[r * PS_STRIDE + j]);
            const float a = __expf(mo - mn);
            float l = rowl[r] * a;
            for (int j = 0; j < 64; j++) {
                const float p = (j < kvalid) ? __expf(Ps[r * PS_STRIDE + j] - mn) : 0.f;
                Ps[r * PS_STRIDE + j] = p;
                l += p;
            }
            rowm[r] = mn; rowl[r] = l; rowa[r] = a;
        }
        __syncthreads();

#pragma unroll
        for (int i = 0; i < 4; i++) {
            const float ai = rowa[ty * 4 + i];
#pragma unroll
            for (int j = 0; j < 8; j++) o[i][j] *= ai;
        }
        for (int j = 0; j < 64; j++) {
            const float4 v0 = *(const float4*)&Vs[j * QKV_STRIDE + tx * 8];
            const float4 v1 = *(const float4*)&Vs[j * QKV_STRIDE + tx * 8 + 4];
#pragma unroll
            for (int i = 0; i < 4; i++) {
                const float p = Ps[(ty * 4 + i) * PS_STRIDE + j];
                o[i][0] += p * v0.x; o[i][1] += p * v0.y;
                o[i][2] += p * v0.z; o[i][3] += p * v0.w;
                o[i][4] += p * v1.x; o[i][5] += p * v1.y;
                o[i][6] += p * v1.z; o[i][7] += p * v1.w;
            }
        }
    }

#pragma unroll
    for (int i = 0; i < 4; i++) {
        const int r = ty * 4 + i;
        const float linv = 1.f / rowl[r];
        float* dst = O + (size_t)(q0 + r) * DIM + head * HDIM + tx * 8;
        float4 o0 = make_float4(o[i][0] * linv, o[i][1] * linv,
                                o[i][2] * linv, o[i][3] * linv);
        float4 o1 = make_float4(o[i][4] * linv, o[i][5] * linv,
                                o[i][6] * linv, o[i][7] * linv);
        *(float4*)(dst)     = o0;
        *(float4*)(dst + 4) = o1;
    }
}

// ---------------------------------------------------------------------------
// Launch
// ---------------------------------------------------------------------------
extern "C" void kernel_launch(void* const* d_in, const int* in_sizes, int n_in,
                              void* d_out, int out_size) {
    const float* x         = (const float*)d_in[0];
    const int*   seq_lens  = (const int*)  d_in[1];
    const int*   grid_sz   = (const int*)  d_in[2];
    const float* freqs     = (const float*)d_in[3];
    const float* wq        = (const float*)d_in[4];
    const float* bq        = (const float*)d_in[5];
    const float* wk        = (const float*)d_in[6];
    const float* bk        = (const float*)d_in[7];
    const float* wv        = (const float*)d_in[8];
    const float* bv        = (const float*)d_in[9];
    const float* wo        = (const float*)d_in[10];
    const float* bo        = (const float*)d_in[11];
    const float* gq        = (const float*)d_in[12];
    const float* gk        = (const float*)d_in[13];
    float* out = (float*)d_out;

    float *q, *k, *v, *attn;
    cudaGetSymbolAddress((void**)&q,    g_q);
    cudaGetSymbolAddress((void**)&k,    g_k);
    cudaGetSymbolAddress((void**)&v,    g_v);
    cudaGetSymbolAddress((void**)&attn, g_attn);

    __nv_bfloat16 *xh, *xl, *ah, *al;
    __nv_bfloat16 *wqh, *wql, *wkh, *wkl, *wvh, *wvl, *woh, *wol;
    cudaGetSymbolAddress((void**)&xh,  g_xh);  cudaGetSymbolAddress((void**)&xl,  g_xl);
    cudaGetSymbolAddress((void**)&ah,  g_ah);  cudaGetSymbolAddress((void**)&al,  g_al);
    cudaGetSymbolAddress((void**)&wqh, g_wqh); cudaGetSymbolAddress((void**)&wql, g_wql);
    cudaGetSymbolAddress((void**)&wkh, g_wkh); cudaGetSymbolAddress((void**)&wkl, g_wkl);
    cudaGetSymbolAddress((void**)&wvh, g_wvh); cudaGetSymbolAddress((void**)&wvl, g_wvl);
    cudaGetSymbolAddress((void**)&woh, g_woh); cudaGetSymbolAddress((void**)&wol, g_wol);

    const int nX = SEQ * DIM, nW = DIM * DIM;
    split_f32<<<nX / 1024, 256>>>(x,  xh,  xl,  nX);
    split_f32<<<nW / 1024, 256>>>(wq, wqh, wql, nW);
    split_f32<<<nW / 1024, 256>>>(wk, wkh, wkl, nW);
    split_f32<<<nW / 1024, 256>>>(wv, wvh, wvl, nW);
    split_f32<<<nW / 1024, 256>>>(wo, woh, wol, nW);

    const dim3 gemm_grid(DIM / 128, SEQ / 128);   // (24, 18)
    gemm_bf16x3<<<gemm_grid, 256>>>(xh, xl, wqh, wql, bq, q, SEQ, DIM, DIM);
    gemm_bf16x3<<<gemm_grid, 256>>>(xh, xl, wkh, wkl, bk, k, SEQ, DIM, DIM);
    gemm_bf16x3<<<gemm_grid, 256>>>(xh, xl, wvh, wvl, bv, v, SEQ, DIM, DIM);

    norm_rope<<<SEQ, 256>>>(q, gq, freqs, grid_sz);
    norm_rope<<<SEQ, 256>>>(k, gk, freqs, grid_sz);

    const size_t smem = (size_t)(3 * 64 * QKV_STRIDE + 64 * PS_STRIDE + 3 * 64) * sizeof(float);
    cudaFuncSetAttribute(flash_kernel, cudaFuncAttributeMaxDynamicSharedMemorySize, (int)smem);
    flash_kernel<<<dim3(SEQ / 64, NHEADS), 256, smem>>>(q, k, v, seq_lens, attn);

    split_f32<<<nX / 1024, 256>>>(attn, ah, al, nX);
    gemm_bf16x3<<<gemm_grid, 256>>>(ah, al, woh, wol, bo, out, SEQ, DIM, DIM);
}

// round 4
// speedup vs baseline: 2.1384x; 1.6462x over previous
#include <cuda_runtime.h>
#include <cuda_bf16.h>
#include <math.h>
#include <stdint.h>

#define DIM    3072
#define NHEADS 24
#define HDIM   128
#define SEQ    2304

// ---------------------------------------------------------------------------
// Scratch (allocation-free: __device__ globals)
// ---------------------------------------------------------------------------
__device__ float g_q[SEQ * DIM];
__device__ float g_k[SEQ * DIM];
__device__ float g_v[SEQ * DIM];

__device__ __nv_bfloat16 g_xh[SEQ * DIM],  g_xl[SEQ * DIM];
__device__ __nv_bfloat16 g_ah[SEQ * DIM],  g_al[SEQ * DIM];
__device__ __nv_bfloat16 g_qh[SEQ * DIM],  g_ql[SEQ * DIM];
__device__ __nv_bfloat16 g_kh[SEQ * DIM],  g_kl[SEQ * DIM];
__device__ __nv_bfloat16 g_vh[SEQ * DIM],  g_vl[SEQ * DIM];
__device__ __nv_bfloat16 g_wqh[DIM * DIM], g_wql[DIM * DIM];
__device__ __nv_bfloat16 g_wkh[DIM * DIM], g_wkl[DIM * DIM];
__device__ __nv_bfloat16 g_wvh[DIM * DIM], g_wvl[DIM * DIM];
__device__ __nv_bfloat16 g_woh[DIM * DIM], g_wol[DIM * DIM];

// fp32 pair -> packed bf16 hi / bf16 lo  (hygienic: function, not macro)
__device__ __forceinline__ uint2 split2(float a, float b) {
    __nv_bfloat162 h = __floats2bfloat162_rn(a, b);
    __nv_bfloat162 l = __floats2bfloat162_rn(a - __bfloat162float(h.x),
                                             b - __bfloat162float(h.y));
    uint2 r;
    r.x = *reinterpret_cast<uint32_t*>(&h);
    r.y = *reinterpret_cast<uint32_t*>(&l);
    return r;
}

// ---------------------------------------------------------------------------
// fp32 -> (bf16 hi, bf16 lo) split.
// ---------------------------------------------------------------------------
__global__ __launch_bounds__(256)
void split_f32(const float* __restrict__ in, __nv_bfloat16* __restrict__ hi,
               __nv_bfloat16* __restrict__ lo, int n) {
    int i = (blockIdx.x * 256 + threadIdx.x) * 4;
    if (i + 3 >= n) return;
    float4 v = *(const float4*)(in + i);
    uint2 p0 = split2(v.x, v.y);
    uint2 p1 = split2(v.z, v.w);
    *(uint2*)(hi + i) = make_uint2(p0.x, p1.x);
    *(uint2*)(lo + i) = make_uint2(p0.y, p1.y);
}

// ---------------------------------------------------------------------------
// bf16x3 tensor-core GEMM (NT) — unchanged from round 2 (passing).
// ---------------------------------------------------------------------------
#define SSTR 20

#define MMA_BF16(d, a, b)                                                     \
    asm volatile("mma.sync.aligned.m16n8k16.row.col.f32.bf16.bf16.f32 "       \
                 "{%0,%1,%2,%3}, {%4,%5,%6,%7}, {%8,%9}, {%0,%1,%2,%3};"      \
                 : "+f"(d[0]), "+f"(d[1]), "+f"(d[2]), "+f"(d[3])             \
                 : "r"(a[0]), "r"(a[1]), "r"(a[2]), "r"(a[3]),                \
                   "r"(b[0]), "r"(b[1]))

__global__ __launch_bounds__(256)
void gemm_bf16x3(const __nv_bfloat16* __restrict__ Ah,
                 const __nv_bfloat16* __restrict__ Al,
                 const __nv_bfloat16* __restrict__ Bh,
                 const __nv_bfloat16* __restrict__ Bl,
                 const float* __restrict__ bias, float* __restrict__ C,
                 int M, int N, int K) {
    __shared__ uint32_t sAh[128 * SSTR], sAl[128 * SSTR];
    __shared__ uint32_t sBh[128 * SSTR], sBl[128 * SSTR];

    const int bm = blockIdx.y * 128, bn = blockIdx.x * 128;
    const int tid = threadIdx.x;
    const int w = tid >> 5, lane = tid & 31;
    const int wm = w & 1, wn = w >> 1;
    const int g = lane >> 2, tg = lane & 3;

    float acc[4][4][4];
#pragma unroll
    for (int mi = 0; mi < 4; mi++)
#pragma unroll
        for (int ni = 0; ni < 4; ni++)
#pragma unroll
            for (int r = 0; r < 4; r++) acc[mi][ni][r] = 0.f;

    for (int kt = 0; kt < K; kt += 32) {
        __syncthreads();
        int idx = tid;
#pragma unroll
        for (int it = 0; it < 2; it++, idx += 256) {
            const int row = idx >> 2, q = idx & 3;
            const size_t ga = (size_t)(bm + row) * K + kt + q * 8;
            const size_t gb = (size_t)(bn + row) * K + kt + q * 8;
            uint4 vah = *(const uint4*)(Ah + ga);
            uint4 val = *(const uint4*)(Al + ga);
            uint4 vbh = *(const uint4*)(Bh + gb);
            uint4 vbl = *(const uint4*)(Bl + gb);
            *(uint4*)&sAh[row * SSTR + q * 4] = vah;
            *(uint4*)&sAl[row * SSTR + q * 4] = val;
            *(uint4*)&sBh[row * SSTR + q * 4] = vbh;
            *(uint4*)&sBl[row * SSTR + q * 4] = vbl;
        }
        __syncthreads();

#pragma unroll
        for (int ks = 0; ks < 2; ks++) {
            const int kb = ks * 8;
            uint32_t ah[4][4], al[4][4], bh[4][2], bl[4][2];
#pragma unroll
            for (int mi = 0; mi < 4; mi++) {
                const int r = wm * 64 + mi * 16 + g;
                ah[mi][0] = sAh[r * SSTR + kb + tg];
                ah[mi][1] = sAh[(r + 8) * SSTR + kb + tg];
                ah[mi][2] = sAh[r * SSTR + kb + tg + 4];
                ah[mi][3] = sAh[(r + 8) * SSTR + kb + tg + 4];
                al[mi][0] = sAl[r * SSTR + kb + tg];
                al[mi][1] = sAl[(r + 8) * SSTR + kb + tg];
                al[mi][2] = sAl[r * SSTR + kb + tg + 4];
                al[mi][3] = sAl[(r + 8) * SSTR + kb + tg + 4];
            }
#pragma unroll
            for (int ni = 0; ni < 4; ni++) {
                const int c = wn * 32 + ni * 8 + g;
                bh[ni][0] = sBh[c * SSTR + kb + tg];
                bh[ni][1] = sBh[c * SSTR + kb + tg + 4];
                bl[ni][0] = sBl[c * SSTR + kb + tg];
                bl[ni][1] = sBl[c * SSTR + kb + tg + 4];
            }
#pragma unroll
            for (int mi = 0; mi < 4; mi++)
#pragma unroll
                for (int ni = 0; ni < 4; ni++) {
                    MMA_BF16(acc[mi][ni], ah[mi], bh[ni]);
                    MMA_BF16(acc[mi][ni], ah[mi], bl[ni]);
                    MMA_BF16(acc[mi][ni], al[mi], bh[ni]);
                }
        }
    }

#pragma unroll
    for (int mi = 0; mi < 4; mi++)
#pragma unroll
        for (int ni = 0; ni < 4; ni++) {
            const int r = bm + wm * 64 + mi * 16 + g;
            const int c = bn + wn * 32 + ni * 8 + tg * 2;
            const float b0 = bias[c], b1 = bias[c + 1];
            C[(size_t)r * N + c]           = acc[mi][ni][0] + b0;
            C[(size_t)r * N + c + 1]       = acc[mi][ni][1] + b1;
            C[(size_t)(r + 8) * N + c]     = acc[mi][ni][2] + b0;
            C[(size_t)(r + 8) * N + c + 1] = acc[mi][ni][3] + b1;
        }
}

// ---------------------------------------------------------------------------
// Fused fp32 RMSNorm + 3-axis RoPE + scale + bf16 hi/lo split.
// ---------------------------------------------------------------------------
__global__ __launch_bounds__(256)
void norm_rope_split(const float* __restrict__ buf, const float* __restrict__ g,
                     const float* __restrict__ freqs,
                     const int* __restrict__ grid_sizes,
                     __nv_bfloat16* __restrict__ oh, __nv_bfloat16* __restrict__ ol,
                     float scale) {
    __shared__ float red[256];
    __shared__ float s_rn;
    const int row = blockIdx.x;
    const int tid = threadIdx.x;
    const float* rp = buf + (size_t)row * DIM;

    float ss = 0.f;
    for (int i = tid; i < DIM; i += 256) { float v = rp[i]; ss += v * v; }
    red[tid] = ss;
    __syncthreads();
#pragma unroll
    for (int st = 128; st > 0; st >>= 1) {
        if (tid < st) red[tid] += red[tid + st];
        __syncthreads();
    }
    if (tid == 0) s_rn = rsqrtf(red[0] / (float)DIM + 1e-6f);
    __syncthreads();
    const float rn = s_rn;

    const int gh = grid_sizes[1];
    const int gw = grid_sizes[2];
    const int fi = row / (gh * gw);
    const int hi = (row % (gh * gw)) / gw;
    const int wi = row % gw;

    for (int p = tid; p < DIM / 2; p += 256) {
        const int c = p & 63;
        const int pos = (c < 22) ? fi : ((c < 43) ? hi : wi);
        const float theta = freqs[pos * 64 + c];
        float sn, cs;
        sincosf(theta, &sn, &cs);
        const int idx = (p >> 6) * HDIM + 2 * c;
        const float xr = rp[idx]     * rn * g[idx];
        const float xi = rp[idx + 1] * rn * g[idx + 1];
        const float y0 = (xr * cs - xi * sn) * scale;
        const float y1 = (xr * sn + xi * cs) * scale;
        uint2 p2 = split2(y0, y1);
        *(uint32_t*)(oh + (size_t)row * DIM + idx) = p2.x;
        *(uint32_t*)(ol + (size_t)row * DIM + idx) = p2.y;
    }
}

// ---------------------------------------------------------------------------
// Tensor-core flash attention, bf16x3 on QK^T and PV, fp32 online softmax.
// BQ=64, BK=64, D=128. 128 threads = 4 warps; warp w owns q-rows [16w,16w+16).
// ---------------------------------------------------------------------------
#define QSTR 68   // u32 stride for Q/K smem rows (64 data + 4 pad)
#define VSTR 35   // u32 stride for V^T smem rows (32 data + 3 pad)

__global__ __launch_bounds__(128, 2)
void flash_mma(const __nv_bfloat16* __restrict__ Qh, const __nv_bfloat16* __restrict__ Ql,
               const __nv_bfloat16* __restrict__ Kh, const __nv_bfloat16* __restrict__ Kl,
               const __nv_bfloat16* __restrict__ Vh, const __nv_bfloat16* __restrict__ Vl,
               const int* __restrict__ seq_lens,
               __nv_bfloat16* __restrict__ Oh, __nv_bfloat16* __restrict__ Ol) {
    extern __shared__ uint32_t sm[];
    uint32_t* sQh = sm;
    uint32_t* sQl = sQh + 64 * QSTR;
    uint32_t* sKh = sQl + 64 * QSTR;
    uint32_t* sKl = sKh + 64 * QSTR;
    uint32_t* sVh = sKl + 64 * QSTR;          // [128][VSTR]  (V transposed: row=dim)
    uint32_t* sVl = sVh + 128 * VSTR;

    const int head = blockIdx.y;
    const int q0 = blockIdx.x * 64;
    const int tid = threadIdx.x;
    const int w = tid >> 5, lane = tid & 31;
    const int g = lane >> 2, tg = lane & 3;
    const int m0 = w * 16;
    const int seqlen = seq_lens[0];
    const int GROW = DIM / 2;   // u32 per global row

    // ---- load Q tile (u32 = 2 bf16), rows q0..q0+63 ----
    {
        const uint32_t* gQh = (const uint32_t*)(Qh + (size_t)q0 * DIM + head * HDIM);
        const uint32_t* gQl = (const uint32_t*)(Ql + (size_t)q0 * DIM + head * HDIM);
        for (int i = tid; i < 64 * 64; i += 128) {
            const int r = i >> 6, c = i & 63;
            sQh[r * QSTR + c] = gQh[(size_t)r * GROW + c];
            sQl[r * QSTR + c] = gQl[(size_t)r * GROW + c];
        }
    }

    float m[2] = {-1e30f, -1e30f}, l[2] = {0.f, 0.f};
    float o[16][4];
#pragma unroll
    for (int n = 0; n < 16; n++)
#pragma unroll
        for (int r = 0; r < 4; r++) o[n][r] = 0.f;

    for (int k0 = 0; k0 < SEQ; k0 += 64) {
        if (k0 >= seqlen) break;
        __syncthreads();
        // ---- load K tile ----
        {
            const uint32_t* gKh = (const uint32_t*)(Kh + (size_t)k0 * DIM + head * HDIM);
            const uint32_t* gKl = (const uint32_t*)(Kl + (size_t)k0 * DIM + head * HDIM);
            for (int i = tid; i < 64 * 64; i += 128) {
                const int r = i >> 6, c = i & 63;
                sKh[r * QSTR + c] = gKh[(size_t)r * GROW + c];
                sKl[r * QSTR + c] = gKl[(size_t)r * GROW + c];
            }
        }
        // ---- load V tile, transpose into [dim][kv] ----
        {
            const uint32_t* gVh = (const uint32_t*)(Vh + (size_t)k0 * DIM + head * HDIM);
            const uint32_t* gVl = (const uint32_t*)(Vl + (size_t)k0 * DIM + head * HDIM);
            __nv_bfloat16* tVh = (__nv_bfloat16*)sVh;
            __nv_bfloat16* tVl = (__nv_bfloat16*)sVl;
            for (int i = tid; i < 64 * 64; i += 128) {
                const int r = i >> 6, du = i & 63;        // kv row, dim-u32
                uint32_t vh = gVh[(size_t)r * GROW + du];
                uint32_t vl = gVl[(size_t)r * GROW + du];
                __nv_bfloat162 vh2 = *reinterpret_cast<__nv_bfloat162*>(&vh);
                __nv_bfloat162 vl2 = *reinterpret_cast<__nv_bfloat162*>(&vl);
                tVh[(2 * du)     * (2 * VSTR) + r] = vh2.x;
                tVh[(2 * du + 1) * (2 * VSTR) + r] = vh2.y;
                tVl[(2 * du)     * (2 * VSTR) + r] = vl2.x;
                tVl[(2 * du + 1) * (2 * VSTR) + r] = vl2.y;
            }
        }
        __syncthreads();

        // ---- scores S = Q K^T  (bf16x3) ----
        float s[8][4];
#pragma unroll
        for (int j = 0; j < 8; j++)
#pragma unroll
            for (int r = 0; r < 4; r++) s[j][r] = 0.f;

#pragma unroll
        for (int ks = 0; ks < 8; ks++) {
            uint32_t ah[4], al[4];
            const int ab = (m0 + g) * QSTR + ks * 8 + tg;
            ah[0] = sQh[ab];            ah[1] = sQh[ab + 8 * QSTR];
            ah[2] = sQh[ab + 4];        ah[3] = sQh[ab + 8 * QSTR + 4];
            al[0] = sQl[ab];            al[1] = sQl[ab + 8 * QSTR];
            al[2] = sQl[ab + 4];        al[3] = sQl[ab + 8 * QSTR + 4];
#pragma unroll
            for (int j = 0; j < 8; j++) {
                uint32_t bh[2], bl[2];
                const int kb = (8 * j + g) * QSTR + ks * 8 + tg;
                bh[0] = sKh[kb]; bh[1] = sKh[kb + 4];
                bl[0] = sKl[kb]; bl[1] = sKl[kb + 4];
                MMA_BF16(s[j], ah, bh);
                MMA_BF16(s[j], ah, bl);
                MMA_BF16(s[j], al, bh);
            }
        }

        // ---- online softmax (rows m0+g and m0+g+8, warp-local) ----
        const int kv = seqlen - k0;  // valid cols this tile
        float mx0 = -1e30f, mx1 = -1e30f;
#pragma unroll
        for (int j = 0; j < 8; j++) {
            const int c0 = 8 * j + 2 * tg, c1 = c0 + 1;
            if (c0 >= kv) { s[j][0] = -1e30f; s[j][2] = -1e30f; }
            if (c1 >= kv) { s[j][1] = -1e30f; s[j][3] = -1e30f; }
            mx0 = fmaxf(mx0, fmaxf(s[j][0], s[j][1]));
            mx1 = fmaxf(mx1, fmaxf(s[j][2], s[j][3]));
        }
        mx0 = fmaxf(mx0, __shfl_xor_sync(0xffffffff, mx0, 1));
        mx0 = fmaxf(mx0, __shfl_xor_sync(0xffffffff, mx0, 2));
        mx1 = fmaxf(mx1, __shfl_xor_sync(0xffffffff, mx1, 1));
        mx1 = fmaxf(mx1, __shfl_xor_sync(0xffffffff, mx1, 2));
        const float mn0 = fmaxf(m[0], mx0);
        const float mn1 = fmaxf(m[1], mx1);
        const float a0 = __expf(m[0] - mn0);
        const float a1 = __expf(m[1] - mn1);
        m[0] = mn0; m[1] = mn1;

        float sum0 = 0.f, sum1 = 0.f;
#pragma unroll
        for (int j = 0; j < 8; j++) {
            s[j][0] = __expf(s[j][0] - mn0);
            s[j][1] = __expf(s[j][1] - mn0);
            s[j][2] = __expf(s[j][2] - mn1);
            s[j][3] = __expf(s[j][3] - mn1);
            sum0 += s[j][0] + s[j][1];
            sum1 += s[j][2] + s[j][3];
        }
        sum0 += __shfl_xor_sync(0xffffffff, sum0, 1);
        sum0 += __shfl_xor_sync(0xffffffff, sum0, 2);
        sum1 += __shfl_xor_sync(0xffffffff, sum1, 1);
        sum1 += __shfl_xor_sync(0xffffffff, sum1, 2);
        l[0] = l[0] * a0 + sum0;
        l[1] = l[1] * a1 + sum1;

#pragma unroll
        for (int n = 0; n < 16; n++) {
            o[n][0] *= a0; o[n][1] *= a0;
            o[n][2] *= a1; o[n][3] *= a1;
        }

        // ---- O += P V  (bf16x3; P fragments built in registers) ----
#pragma unroll
        for (int kp = 0; kp < 4; kp++) {
            uint32_t ph[4], pl[4];
            const int j0 = 2 * kp, j1 = 2 * kp + 1;
            uint2 t;
            t = split2(s[j0][0], s[j0][1]); ph[0] = t.x; pl[0] = t.y;
            t = split2(s[j0][2], s[j0][3]); ph[1] = t.x; pl[1] = t.y;
            t = split2(s[j1][0], s[j1][1]); ph[2] = t.x; pl[2] = t.y;
            t = split2(s[j1][2], s[j1][3]); ph[3] = t.x; pl[3] = t.y;
#pragma unroll
            for (int n = 0; n < 16; n++) {
                uint32_t bh[2], bl[2];
                const int vb = (8 * n + g) * VSTR + kp * 8 + tg;
                bh[0] = sVh[vb]; bh[1] = sVh[vb + 4];
                bl[0] = sVl[vb]; bl[1] = sVl[vb + 4];
                MMA_BF16(o[n], ph, bh);
                MMA_BF16(o[n], ph, bl);
                MMA_BF16(o[n], pl, bh);
            }
        }
    }

    // ---- epilogue: normalize and write bf16 hi/lo ----
    const float inv0 = 1.f / l[0];
    const float inv1 = 1.f / l[1];
    const int r0 = q0 + m0 + g;
    const int r1 = r0 + 8;
    uint32_t* oHh = (uint32_t*)(Oh);
    uint32_t* oLl = (uint32_t*)(Ol);
#pragma unroll
    for (int n = 0; n < 16; n++) {
        const int col = head * HDIM + 8 * n + 2 * tg;   // even
        uint2 p0 = split2(o[n][0] * inv0, o[n][1] * inv0);
        oHh[(size_t)r0 * GROW + col / 2] = p0.x;
        oLl[(size_t)r0 * GROW + col / 2] = p0.y;
        uint2 p1 = split2(o[n][2] * inv1, o[n][3] * inv1);
        oHh[(size_t)r1 * GROW + col / 2] = p1.x;
        oLl[(size_t)r1 * GROW + col / 2] = p1.y;
    }
}

// ---------------------------------------------------------------------------
// Launch
// ---------------------------------------------------------------------------
extern "C" void kernel_launch(void* const* d_in, const int* in_sizes, int n_in,
                              void* d_out, int out_size) {
    const float* x         = (const float*)d_in[0];
    const int*   seq_lens  = (const int*)  d_in[1];
    const int*   grid_sz   = (const int*)  d_in[2];
    const float* freqs     = (const float*)d_in[3];
    const float* wq        = (const float*)d_in[4];
    const float* bq        = (const float*)d_in[5];
    const float* wk        = (const float*)d_in[6];
    const float* bk        = (const float*)d_in[7];
    const float* wv        = (const float*)d_in[8];
    const float* bv        = (const float*)d_in[9];
    const float* wo        = (const float*)d_in[10];
    const float* bo        = (const float*)d_in[11];
    const float* gq        = (const float*)d_in[12];
    const float* gk        = (const float*)d_in[13];
    float* out = (float*)d_out;

    float *q, *k, *v;
    cudaGetSymbolAddress((void**)&q, g_q);
    cudaGetSymbolAddress((void**)&k, g_k);
    cudaGetSymbolAddress((void**)&v, g_v);

    __nv_bfloat16 *xh, *xl, *ah, *al, *qh, *ql, *kh, *kl, *vh, *vl;
    __nv_bfloat16 *wqh, *wql, *wkh, *wkl, *wvh, *wvl, *woh, *wol;
    cudaGetSymbolAddress((void**)&xh,  g_xh);  cudaGetSymbolAddress((void**)&xl,  g_xl);
    cudaGetSymbolAddress((void**)&ah,  g_ah);  cudaGetSymbolAddress((void**)&al,  g_al);
    cudaGetSymbolAddress((void**)&qh,  g_qh);  cudaGetSymbolAddress((void**)&ql,  g_ql);
    cudaGetSymbolAddress((void**)&kh,  g_kh);  cudaGetSymbolAddress((void**)&kl,  g_kl);
    cudaGetSymbolAddress((void**)&vh,  g_vh);  cudaGetSymbolAddress((void**)&vl,  g_vl);
    cudaGetSymbolAddress((void**)&wqh, g_wqh); cudaGetSymbolAddress((void**)&wql, g_wql);
    cudaGetSymbolAddress((void**)&wkh, g_wkh); cudaGetSymbolAddress((void**)&wkl, g_wkl);
    cudaGetSymbolAddress((void**)&wvh, g_wvh); cudaGetSymbolAddress((void**)&wvl, g_wvl);
    cudaGetSymbolAddress((void**)&woh, g_woh); cudaGetSymbolAddress((void**)&wol, g_wol);

    const int nX = SEQ * DIM, nW = DIM * DIM;
    split_f32<<<nX / 1024, 256>>>(x,  xh,  xl,  nX);
    split_f32<<<nW / 1024, 256>>>(wq, wqh, wql, nW);
    split_f32<<<nW / 1024, 256>>>(wk, wkh, wkl, nW);
    split_f32<<<nW / 1024, 256>>>(wv, wvh, wvl, nW);
    split_f32<<<nW / 1024, 256>>>(wo, woh, wol, nW);

    const dim3 gemm_grid(DIM / 128, SEQ / 128);
    gemm_bf16x3<<<gemm_grid, 256>>>(xh, xl, wqh, wql, bq, q, SEQ, DIM, DIM);
    gemm_bf16x3<<<gemm_grid, 256>>>(xh, xl, wkh, wkl, bk, k, SEQ, DIM, DIM);
    gemm_bf16x3<<<gemm_grid, 256>>>(xh, xl, wvh, wvl, bv, v, SEQ, DIM, DIM);

    const float scale = 0.08838834764831845f;   // 1/sqrt(128)
    norm_rope_split<<<SEQ, 256>>>(q, gq, freqs, grid_sz, qh, ql, scale);
    norm_rope_split<<<SEQ, 256>>>(k, gk, freqs, grid_sz, kh, kl, 1.0f);
    split_f32<<<nX / 1024, 256>>>(v, vh, vl, nX);

    const size_t fl_smem = (size_t)(4 * 64 * QSTR + 2 * 128 * VSTR) * sizeof(uint32_t);
    cudaFuncSetAttribute(flash_mma, cudaFuncAttributeMaxDynamicSharedMemorySize, (int)fl_smem);
    flash_mma<<<dim3(SEQ / 64, NHEADS), 128, fl_smem>>>(qh, ql, kh, kl, vh, vl,
                                                        seq_lens, ah, al);

    gemm_bf16x3<<<gemm_grid, 256>>>(ah, al, woh, wol, bo, out, SEQ, DIM, DIM);
}

// round 5
// speedup vs baseline: 2.5748x; 1.2041x over previous
#include <cuda_runtime.h>
#include <cuda_bf16.h>
#include <math.h>
#include <stdint.h>

#define DIM    3072
#define NHEADS 24
#define HDIM   128
#define SEQ    2304

// ---------------------------------------------------------------------------
// Scratch (allocation-free: __device__ globals)
// ---------------------------------------------------------------------------
__device__ float g_q[SEQ * DIM];
__device__ float g_k[SEQ * DIM];
__device__ float g_v[SEQ * DIM];

__device__ __nv_bfloat16 g_xh[SEQ * DIM],  g_xl[SEQ * DIM];
__device__ __nv_bfloat16 g_ah[SEQ * DIM],  g_al[SEQ * DIM];
__device__ __nv_bfloat16 g_qh[SEQ * DIM],  g_ql[SEQ * DIM];
__device__ __nv_bfloat16 g_kh[SEQ * DIM],  g_kl[SEQ * DIM];
__device__ __nv_bfloat16 g_vh[SEQ * DIM],  g_vl[SEQ * DIM];
__device__ __nv_bfloat16 g_wqh[DIM * DIM], g_wql[DIM * DIM];
__device__ __nv_bfloat16 g_wkh[DIM * DIM], g_wkl[DIM * DIM];
__device__ __nv_bfloat16 g_wvh[DIM * DIM], g_wvl[DIM * DIM];
__device__ __nv_bfloat16 g_woh[DIM * DIM], g_wol[DIM * DIM];

// fp32 pair -> packed bf16 hi / bf16 lo
__device__ __forceinline__ uint2 split2(float a, float b) {
    __nv_bfloat162 h = __floats2bfloat162_rn(a, b);
    __nv_bfloat162 l = __floats2bfloat162_rn(a - __bfloat162float(h.x),
                                             b - __bfloat162float(h.y));
    uint2 r;
    r.x = *reinterpret_cast<uint32_t*>(&h);
    r.y = *reinterpret_cast<uint32_t*>(&l);
    return r;
}

__device__ __forceinline__ void cp16(uint32_t saddr, const void* gptr) {
    asm volatile("cp.async.cg.shared.global [%0], [%1], 16;"
                 :: "r"(saddr), "l"(gptr));
}

// ---------------------------------------------------------------------------
// fp32 -> (bf16 hi, bf16 lo) split.
// ---------------------------------------------------------------------------
__global__ __launch_bounds__(256)
void split_f32(const float* __restrict__ in, __nv_bfloat16* __restrict__ hi,
               __nv_bfloat16* __restrict__ lo, int n) {
    int i = (blockIdx.x * 256 + threadIdx.x) * 4;
    if (i + 3 >= n) return;
    float4 v = *(const float4*)(in + i);
    uint2 p0 = split2(v.x, v.y);
    uint2 p1 = split2(v.z, v.w);
    *(uint2*)(hi + i) = make_uint2(p0.x, p1.x);
    *(uint2*)(lo + i) = make_uint2(p0.y, p1.y);
}

// ---------------------------------------------------------------------------
// bf16x3 tensor-core GEMM (NT), cp.async 2-stage pipeline, batched over z.
// C[m][n] = sum_k A[m][k]*B[n][k] + bias[n].  BM=BN=128, BK=32.
// 256 threads = 8 warps (2M x 4N), warp tile 64x32, mma.m16n8k16.
// ---------------------------------------------------------------------------
#define SSTR 20                       // u32 per smem row (16 data + 4 pad)
#define STG_U32 (4 * 128 * SSTR)      // u32 per stage (4 arrays)
#define ARR_U32 (128 * SSTR)

#define MMA_BF16(d, a, b)                                                     \
    asm volatile("mma.sync.aligned.m16n8k16.row.col.f32.bf16.bf16.f32 "       \
                 "{%0,%1,%2,%3}, {%4,%5,%6,%7}, {%8,%9}, {%0,%1,%2,%3};"      \
                 : "+f"(d[0]), "+f"(d[1]), "+f"(d[2]), "+f"(d[3])             \
                 : "r"(a[0]), "r"(a[1]), "r"(a[2]), "r"(a[3]),                \
                   "r"(b[0]), "r"(b[1]))

struct GemmBatch {
    const __nv_bfloat16* Bh[3];
    const __nv_bfloat16* Bl[3];
    const float*         bias[3];
    float*               C[3];
};

__global__ __launch_bounds__(256)
void gemm_bf16x3_pipe(const __nv_bfloat16* __restrict__ Ah,
                      const __nv_bfloat16* __restrict__ Al,
                      GemmBatch batch, int M, int N, int K) {
    extern __shared__ uint32_t smem[];
    const uint32_t sbase = (uint32_t)__cvta_generic_to_shared(smem);

    const __nv_bfloat16* __restrict__ Bh = batch.Bh[blockIdx.z];
    const __nv_bfloat16* __restrict__ Bl = batch.Bl[blockIdx.z];
    const float* __restrict__ bias = batch.bias[blockIdx.z];
    float* __restrict__ C = batch.C[blockIdx.z];

    const int bm = blockIdx.y * 128, bn = blockIdx.x * 128;
    const int tid = threadIdx.x;
    const int w = tid >> 5, lane = tid & 31;
    const int wm = w & 1, wn = w >> 1;
    const int g = lane >> 2, tg = lane & 3;

    // loader mapping: 512 16B-chunks per array per stage, 2 per thread
    const int c0 = tid, c1 = tid + 256;
    const int r0 = c0 >> 2, q0 = c0 & 3;
    const int r1 = c1 >> 2, q1 = c1 & 3;

    float acc[4][4][4];
#pragma unroll
    for (int mi = 0; mi < 4; mi++)
#pragma unroll
        for (int ni = 0; ni < 4; ni++)
#pragma unroll
            for (int r = 0; r < 4; r++) acc[mi][ni][r] = 0.f;

    auto issue = [&](int kt, int stage) {
        const uint32_t sb = sbase + (uint32_t)stage * STG_U32 * 4;
        const uint32_t oA0 = (r0 * SSTR + q0 * 4) * 4;
        const uint32_t oA1 = (r1 * SSTR + q1 * 4) * 4;
        const size_t ga0 = (size_t)(bm + r0) * K + kt + q0 * 8;
        const size_t ga1 = (size_t)(bm + r1) * K + kt + q1 * 8;
        const size_t gb0 = (size_t)(bn + r0) * K + kt + q0 * 8;
        const size_t gb1 = (size_t)(bn + r1) * K + kt + q1 * 8;
        cp16(sb + oA0,                  Ah + ga0);
        cp16(sb + oA1,                  Ah + ga1);
        cp16(sb + ARR_U32 * 4 + oA0,    Al + ga0);
        cp16(sb + ARR_U32 * 4 + oA1,    Al + ga1);
        cp16(sb + ARR_U32 * 8 + oA0,    Bh + gb0);
        cp16(sb + ARR_U32 * 8 + oA1,    Bh + gb1);
        cp16(sb + ARR_U32 * 12 + oA0,   Bl + gb0);
        cp16(sb + ARR_U32 * 12 + oA1,   Bl + gb1);
    };

    const int ntiles = K / 32;
    issue(0, 0);
    asm volatile("cp.async.commit_group;");

    for (int t = 0; t < ntiles; t++) {
        if (t + 1 < ntiles) issue((t + 1) * 32, (t + 1) & 1);
        asm volatile("cp.async.commit_group;");
        asm volatile("cp.async.wait_group 1;");
        __syncthreads();

        const uint32_t* sAh = smem + (t & 1) * STG_U32;
        const uint32_t* sAl = sAh + ARR_U32;
        const uint32_t* sBh = sAl + ARR_U32;
        const uint32_t* sBl = sBh + ARR_U32;

#pragma unroll
        for (int ks = 0; ks < 2; ks++) {
            const int kb = ks * 8;
            uint32_t ah[4][4], al[4][4], bh[4][2], bl[4][2];
#pragma unroll
            for (int mi = 0; mi < 4; mi++) {
                const int r = wm * 64 + mi * 16 + g;
                ah[mi][0] = sAh[r * SSTR + kb + tg];
                ah[mi][1] = sAh[(r + 8) * SSTR + kb + tg];
                ah[mi][2] = sAh[r * SSTR + kb + tg + 4];
                ah[mi][3] = sAh[(r + 8) * SSTR + kb + tg + 4];
                al[mi][0] = sAl[r * SSTR + kb + tg];
                al[mi][1] = sAl[(r + 8) * SSTR + kb + tg];
                al[mi][2] = sAl[r * SSTR + kb + tg + 4];
                al[mi][3] = sAl[(r + 8) * SSTR + kb + tg + 4];
            }
#pragma unroll
            for (int ni = 0; ni < 4; ni++) {
                const int c = wn * 32 + ni * 8 + g;
                bh[ni][0] = sBh[c * SSTR + kb + tg];
                bh[ni][1] = sBh[c * SSTR + kb + tg + 4];
                bl[ni][0] = sBl[c * SSTR + kb + tg];
                bl[ni][1] = sBl[c * SSTR + kb + tg + 4];
            }
#pragma unroll
            for (int mi = 0; mi < 4; mi++)
#pragma unroll
                for (int ni = 0; ni < 4; ni++) {
                    MMA_BF16(acc[mi][ni], ah[mi], bh[ni]);
                    MMA_BF16(acc[mi][ni], ah[mi], bl[ni]);
                    MMA_BF16(acc[mi][ni], al[mi], bh[ni]);
                }
        }
        __syncthreads();
    }

#pragma unroll
    for (int mi = 0; mi < 4; mi++)
#pragma unroll
        for (int ni = 0; ni < 4; ni++) {
            const int r = bm + wm * 64 + mi * 16 + g;
            const int c = bn + wn * 32 + ni * 8 + tg * 2;
            const float b0 = bias[c], b1 = bias[c + 1];
            C[(size_t)r * N + c]           = acc[mi][ni][0] + b0;
            C[(size_t)r * N + c + 1]       = acc[mi][ni][1] + b1;
            C[(size_t)(r + 8) * N + c]     = acc[mi][ni][2] + b0;
            C[(size_t)(r + 8) * N + c + 1] = acc[mi][ni][3] + b1;
        }
}

// ---------------------------------------------------------------------------
// Fused fp32 RMSNorm + 3-axis RoPE + scale + bf16 hi/lo split.
// ---------------------------------------------------------------------------
__global__ __launch_bounds__(256)
void norm_rope_split(const float* __restrict__ buf, const float* __restrict__ g,
                     const float* __restrict__ freqs,
                     const int* __restrict__ grid_sizes,
                     __nv_bfloat16* __restrict__ oh, __nv_bfloat16* __restrict__ ol,
                     float scale) {
    __shared__ float red[256];
    __shared__ float s_rn;
    const int row = blockIdx.x;
    const int tid = threadIdx.x;
    const float* rp = buf + (size_t)row * DIM;

    float ss = 0.f;
    for (int i = tid; i < DIM; i += 256) { float v = rp[i]; ss += v * v; }
    red[tid] = ss;
    __syncthreads();
#pragma unroll
    for (int st = 128; st > 0; st >>= 1) {
        if (tid < st) red[tid] += red[tid + st];
        __syncthreads();
    }
    if (tid == 0) s_rn = rsqrtf(red[0] / (float)DIM + 1e-6f);
    __syncthreads();
    const float rn = s_rn;

    const int gh = grid_sizes[1];
    const int gw = grid_sizes[2];
    const int fi = row / (gh * gw);
    const int hi = (row % (gh * gw)) / gw;
    const int wi = row % gw;

    for (int p = tid; p < DIM / 2; p += 256) {
        const int c = p & 63;
        const int pos = (c < 22) ? fi : ((c < 43) ? hi : wi);
        const float theta = freqs[pos * 64 + c];
        float sn, cs;
        sincosf(theta, &sn, &cs);
        const int idx = (p >> 6) * HDIM + 2 * c;
        const float xr = rp[idx]     * rn * g[idx];
        const float xi = rp[idx + 1] * rn * g[idx + 1];
        const float y0 = (xr * cs - xi * sn) * scale;
        const float y1 = (xr * sn + xi * cs) * scale;
        uint2 p2 = split2(y0, y1);
        *(uint32_t*)(oh + (size_t)row * DIM + idx) = p2.x;
        *(uint32_t*)(ol + (size_t)row * DIM + idx) = p2.y;
    }
}

// ---------------------------------------------------------------------------
// Tensor-core flash attention (unchanged, passing).
// ---------------------------------------------------------------------------
#define QSTR 68
#define VSTR 35

__global__ __launch_bounds__(128, 2)
void flash_mma(const __nv_bfloat16* __restrict__ Qh, const __nv_bfloat16* __restrict__ Ql,
               const __nv_bfloat16* __restrict__ Kh, const __nv_bfloat16* __restrict__ Kl,
               const __nv_bfloat16* __restrict__ Vh, const __nv_bfloat16* __restrict__ Vl,
               const int* __restrict__ seq_lens,
               __nv_bfloat16* __restrict__ Oh, __nv_bfloat16* __restrict__ Ol) {
    extern __shared__ uint32_t sm[];
    uint32_t* sQh = sm;
    uint32_t* sQl = sQh + 64 * QSTR;
    uint32_t* sKh = sQl + 64 * QSTR;
    uint32_t* sKl = sKh + 64 * QSTR;
    uint32_t* sVh = sKl + 64 * QSTR;
    uint32_t* sVl = sVh + 128 * VSTR;

    const int head = blockIdx.y;
    const int q0 = blockIdx.x * 64;
    const int tid = threadIdx.x;
    const int w = tid >> 5, lane = tid & 31;
    const int g = lane >> 2, tg = lane & 3;
    const int m0 = w * 16;
    const int seqlen = seq_lens[0];
    const int GROW = DIM / 2;

    {
        const uint32_t* gQh = (const uint32_t*)(Qh + (size_t)q0 * DIM + head * HDIM);
        const uint32_t* gQl = (const uint32_t*)(Ql + (size_t)q0 * DIM + head * HDIM);
        for (int i = tid; i < 64 * 64; i += 128) {
            const int r = i >> 6, c = i & 63;
            sQh[r * QSTR + c] = gQh[(size_t)r * GROW + c];
            sQl[r * QSTR + c] = gQl[(size_t)r * GROW + c];
        }
    }

    float m[2] = {-1e30f, -1e30f}, l[2] = {0.f, 0.f};
    float o[16][4];
#pragma unroll
    for (int n = 0; n < 16; n++)
#pragma unroll
        for (int r = 0; r < 4; r++) o[n][r] = 0.f;

    for (int k0 = 0; k0 < SEQ; k0 += 64) {
        if (k0 >= seqlen) break;
        __syncthreads();
        {
            const uint32_t* gKh = (const uint32_t*)(Kh + (size_t)k0 * DIM + head * HDIM);
            const uint32_t* gKl = (const uint32_t*)(Kl + (size_t)k0 * DIM + head * HDIM);
            for (int i = tid; i < 64 * 64; i += 128) {
                const int r = i >> 6, c = i & 63;
                sKh[r * QSTR + c] = gKh[(size_t)r * GROW + c];
                sKl[r * QSTR + c] = gKl[(size_t)r * GROW + c];
            }
        }
        {
            const uint32_t* gVh = (const uint32_t*)(Vh + (size_t)k0 * DIM + head * HDIM);
            const uint32_t* gVl = (const uint32_t*)(Vl + (size_t)k0 * DIM + head * HDIM);
            __nv_bfloat16* tVh = (__nv_bfloat16*)sVh;
            __nv_bfloat16* tVl = (__nv_bfloat16*)sVl;
            for (int i = tid; i < 64 * 64; i += 128) {
                const int r = i >> 6, du = i & 63;
                uint32_t vh = gVh[(size_t)r * GROW + du];
                uint32_t vl = gVl[(size_t)r * GROW + du];
                __nv_bfloat162 vh2 = *reinterpret_cast<__nv_bfloat162*>(&vh);
                __nv_bfloat162 vl2 = *reinterpret_cast<__nv_bfloat162*>(&vl);
                tVh[(2 * du)     * (2 * VSTR) + r] = vh2.x;
                tVh[(2 * du + 1) * (2 * VSTR) + r] = vh2.y;
                tVl[(2 * du)     * (2 * VSTR) + r] = vl2.x;
                tVl[(2 * du + 1) * (2 * VSTR) + r] = vl2.y;
            }
        }
        __syncthreads();

        float s[8][4];
#pragma unroll
        for (int j = 0; j < 8; j++)
#pragma unroll
            for (int r = 0; r < 4; r++) s[j][r] = 0.f;

#pragma unroll
        for (int ks = 0; ks < 8; ks++) {
            uint32_t ah[4], al[4];
            const int ab = (m0 + g) * QSTR + ks * 8 + tg;
            ah[0] = sQh[ab];            ah[1] = sQh[ab + 8 * QSTR];
            ah[2] = sQh[ab + 4];        ah[3] = sQh[ab + 8 * QSTR + 4];
            al[0] = sQl[ab];            al[1] = sQl[ab + 8 * QSTR];
            al[2] = sQl[ab + 4];        al[3] = sQl[ab + 8 * QSTR + 4];
#pragma unroll
            for (int j = 0; j < 8; j++) {
                uint32_t bh[2], bl[2];
                const int kb = (8 * j + g) * QSTR + ks * 8 + tg;
                bh[0] = sKh[kb]; bh[1] = sKh[kb + 4];
                bl[0] = sKl[kb]; bl[1] = sKl[kb + 4];
                MMA_BF16(s[j], ah, bh);
                MMA_BF16(s[j], ah, bl);
                MMA_BF16(s[j], al, bh);
            }
        }

        const int kv = seqlen - k0;
        float mx0 = -1e30f, mx1 = -1e30f;
#pragma unroll
        for (int j = 0; j < 8; j++) {
            const int c0 = 8 * j + 2 * tg, c1 = c0 + 1;
            if (c0 >= kv) { s[j][0] = -1e30f; s[j][2] = -1e30f; }
            if (c1 >= kv) { s[j][1] = -1e30f; s[j][3] = -1e30f; }
            mx0 = fmaxf(mx0, fmaxf(s[j][0], s[j][1]));
            mx1 = fmaxf(mx1, fmaxf(s[j][2], s[j][3]));
        }
        mx0 = fmaxf(mx0, __shfl_xor_sync(0xffffffff, mx0, 1));
        mx0 = fmaxf(mx0, __shfl_xor_sync(0xffffffff, mx0, 2));
        mx1 = fmaxf(mx1, __shfl_xor_sync(0xffffffff, mx1, 1));
        mx1 = fmaxf(mx1, __shfl_xor_sync(0xffffffff, mx1, 2));
        const float mn0 = fmaxf(m[0], mx0);
        const float mn1 = fmaxf(m[1], mx1);
        const float a0 = __expf(m[0] - mn0);
        const float a1 = __expf(m[1] - mn1);
        m[0] = mn0; m[1] = mn1;

        float sum0 = 0.f, sum1 = 0.f;
#pragma unroll
        for (int j = 0; j < 8; j++) {
            s[j][0] = __expf(s[j][0] - mn0);
            s[j][1] = __expf(s[j][1] - mn0);
            s[j][2] = __expf(s[j][2] - mn1);
            s[j][3] = __expf(s[j][3] - mn1);
            sum0 += s[j][0] + s[j][1];
            sum1 += s[j][2] + s[j][3];
        }
        sum0 += __shfl_xor_sync(0xffffffff, sum0, 1);
        sum0 += __shfl_xor_sync(0xffffffff, sum0, 2);
        sum1 += __shfl_xor_sync(0xffffffff, sum1, 1);
        sum1 += __shfl_xor_sync(0xffffffff, sum1, 2);
        l[0] = l[0] * a0 + sum0;
        l[1] = l[1] * a1 + sum1;

#pragma unroll
        for (int n = 0; n < 16; n++) {
            o[n][0] *= a0; o[n][1] *= a0;
            o[n][2] *= a1; o[n][3] *= a1;
        }

#pragma unroll
        for (int kp = 0; kp < 4; kp++) {
            uint32_t ph[4], pl[4];
            const int j0 = 2 * kp, j1 = 2 * kp + 1;
            uint2 t;
            t = split2(s[j0][0], s[j0][1]); ph[0] = t.x; pl[0] = t.y;
            t = split2(s[j0][2], s[j0][3]); ph[1] = t.x; pl[1] = t.y;
            t = split2(s[j1][0], s[j1][1]); ph[2] = t.x; pl[2] = t.y;
            t = split2(s[j1][2], s[j1][3]); ph[3] = t.x; pl[3] = t.y;
#pragma unroll
            for (int n = 0; n < 16; n++) {
                uint32_t bh[2], bl[2];
                const int vb = (8 * n + g) * VSTR + kp * 8 + tg;
                bh[0] = sVh[vb]; bh[1] = sVh[vb + 4];
                bl[0] = sVl[vb]; bl[1] = sVl[vb + 4];
                MMA_BF16(o[n], ph, bh);
                MMA_BF16(o[n], ph, bl);
                MMA_BF16(o[n], pl, bh);
            }
        }
    }

    const float inv0 = 1.f / l[0];
    const float inv1 = 1.f / l[1];
    const int r0 = q0 + m0 + g;
    const int r1 = r0 + 8;
    uint32_t* oHh = (uint32_t*)(Oh);
    uint32_t* oLl = (uint32_t*)(Ol);
#pragma unroll
    for (int n = 0; n < 16; n++) {
        const int col = head * HDIM + 8 * n + 2 * tg;
        uint2 p0 = split2(o[n][0] * inv0, o[n][1] * inv0);
        oHh[(size_t)r0 * GROW + col / 2] = p0.x;
        oLl[(size_t)r0 * GROW + col / 2] = p0.y;
        uint2 p1 = split2(o[n][2] * inv1, o[n][3] * inv1);
        oHh[(size_t)r1 * GROW + col / 2] = p1.x;
        oLl[(size_t)r1 * GROW + col / 2] = p1.y;
    }
}

// ---------------------------------------------------------------------------
// Launch
// ---------------------------------------------------------------------------
extern "C" void kernel_launch(void* const* d_in, const int* in_sizes, int n_in,
                              void* d_out, int out_size) {
    const float* x         = (const float*)d_in[0];
    const int*   seq_lens  = (const int*)  d_in[1];
    const int*   grid_sz   = (const int*)  d_in[2];
    const float* freqs     = (const float*)d_in[3];
    const float* wq        = (const float*)d_in[4];
    const float* bq        = (const float*)d_in[5];
    const float* wk        = (const float*)d_in[6];
    const float* bk        = (const float*)d_in[7];
    const float* wv        = (const float*)d_in[8];
    const float* bv        = (const float*)d_in[9];
    const float* wo        = (const float*)d_in[10];
    const float* bo        = (const float*)d_in[11];
    const float* gq        = (const float*)d_in[12];
    const float* gk        = (const float*)d_in[13];
    float* out = (float*)d_out;

    float *q, *k, *v;
    cudaGetSymbolAddress((void**)&q, g_q);
    cudaGetSymbolAddress((void**)&k, g_k);
    cudaGetSymbolAddress((void**)&v, g_v);

    __nv_bfloat16 *xh, *xl, *ah, *al, *qh, *ql, *kh, *kl, *vh, *vl;
    __nv_bfloat16 *wqh, *wql, *wkh, *wkl, *wvh, *wvl, *woh, *wol;
    cudaGetSymbolAddress((void**)&xh,  g_xh);  cudaGetSymbolAddress((void**)&xl,  g_xl);
    cudaGetSymbolAddress((void**)&ah,  g_ah);  cudaGetSymbolAddress((void**)&al,  g_al);
    cudaGetSymbolAddress((void**)&qh,  g_qh);  cudaGetSymbolAddress((void**)&ql,  g_ql);
    cudaGetSymbolAddress((void**)&kh,  g_kh);  cudaGetSymbolAddress((void**)&kl,  g_kl);
    cudaGetSymbolAddress((void**)&vh,  g_vh);  cudaGetSymbolAddress((void**)&vl,  g_vl);
    cudaGetSymbolAddress((void**)&wqh, g_wqh); cudaGetSymbolAddress((void**)&wql, g_wql);
    cudaGetSymbolAddress((void**)&wkh, g_wkh); cudaGetSymbolAddress((void**)&wkl, g_wkl);
    cudaGetSymbolAddress((void**)&wvh, g_wvh); cudaGetSymbolAddress((void**)&wvl, g_wvl);
    cudaGetSymbolAddress((void**)&woh, g_woh); cudaGetSymbolAddress((void**)&wol, g_wol);

    const int nX = SEQ * DIM, nW = DIM * DIM;
    split_f32<<<nX / 1024, 256>>>(x,  xh,  xl,  nX);
    split_f32<<<nW / 1024, 256>>>(wq, wqh, wql, nW);
    split_f32<<<nW / 1024, 256>>>(wk, wkh, wkl, nW);
    split_f32<<<nW / 1024, 256>>>(wv, wvh, wvl, nW);
    split_f32<<<nW / 1024, 256>>>(wo, woh, wol, nW);

    const int gemm_smem = 2 * STG_U32 * 4;   // 81920 bytes
    cudaFuncSetAttribute(gemm_bf16x3_pipe,
                         cudaFuncAttributeMaxDynamicSharedMemorySize, gemm_smem);

    // fused QKV projections
    GemmBatch qkv;
    qkv.Bh[0] = wqh; qkv.Bl[0] = wql; qkv.bias[0] = bq; qkv.C[0] = q;
    qkv.Bh[1] = wkh; qkv.Bl[1] = wkl; qkv.bias[1] = bk; qkv.C[1] = k;
    qkv.Bh[2] = wvh; qkv.Bl[2] = wvl; qkv.bias[2] = bv; qkv.C[2] = v;
    gemm_bf16x3_pipe<<<dim3(DIM / 128, SEQ / 128, 3), 256, gemm_smem>>>(
        xh, xl, qkv, SEQ, DIM, DIM);

    const float scale = 0.08838834764831845f;   // 1/sqrt(128)
    norm_rope_split<<<SEQ, 256>>>(q, gq, freqs, grid_sz, qh, ql, scale);
    norm_rope_split<<<SEQ, 256>>>(k, gk, freqs, grid_sz, kh, kl, 1.0f);
    split_f32<<<nX / 1024, 256>>>(v, vh, vl, nX);

    const size_t fl_smem = (size_t)(4 * 64 * QSTR + 2 * 128 * VSTR) * sizeof(uint32_t);
    cudaFuncSetAttribute(flash_mma, cudaFuncAttributeMaxDynamicSharedMemorySize, (int)fl_smem);
    flash_mma<<<dim3(SEQ / 64, NHEADS), 128, fl_smem>>>(qh, ql, kh, kl, vh, vl,
                                                        seq_lens, ah, al);

    // output projection
    GemmBatch ob;
    ob.Bh[0] = woh; ob.Bl[0] = wol; ob.bias[0] = bo; ob.C[0] = out;
    ob.Bh[1] = woh; ob.Bl[1] = wol; ob.bias[1] = bo; ob.C[1] = out;
    ob.Bh[2] = woh; ob.Bl[2] = wol; ob.bias[2] = bo; ob.C[2] = out;
    gemm_bf16x3_pipe<<<dim3(DIM / 128, SEQ / 128, 1), 256, gemm_smem>>>(
        ah, al, ob, SEQ, DIM, DIM);
}